// round 6
// baseline (speedup 1.0000x reference)
#include <cuda_runtime.h>
#include <cuda_fp16.h>
#include <cstdint>
#include <cstddef>

// ---------------- problem constants ----------------
static constexpr int G    = 32;     // algebra dim
static constexpr int IO   = 128;    // in_o = out_o
static constexpr int NTOK = 8192;   // B*T
static constexpr int WN   = G * IO * IO;                    // 524288 weights
static constexpr size_t XM_ELEMS = (size_t)G * NTOK * IO;   // 33.5M

// ---------------- scratch (device globals: allowed) ----------------
__device__ __half g_xm[XM_ELEMS];       // [h][t][i]  fp16
__device__ __half g_yp[XM_ELEMS];       // [h][t][o]  fp16
__device__ __half g_wq[WN];             // [h][o][i]  ternary fp16 (unscaled)
__device__ float  g_partials[512];
__device__ float  g_scale;

// ---------------- PTX helpers (portable: sm_80-era, valid on compute_103) --------
__device__ __forceinline__ uint32_t smem_u32(const void* p) {
    uint32_t a;
    asm("{ .reg .u64 t; cvta.to.shared.u64 t, %1; cvt.u32.u64 %0, t; }" : "=r"(a) : "l"(p));
    return a;
}
__device__ __forceinline__ void ldsm_x4(uint32_t& r0, uint32_t& r1, uint32_t& r2, uint32_t& r3,
                                        uint32_t addr) {
    asm volatile("ldmatrix.sync.aligned.m8n8.x4.shared.b16 {%0,%1,%2,%3}, [%4];"
                 : "=r"(r0), "=r"(r1), "=r"(r2), "=r"(r3) : "r"(addr));
}
__device__ __forceinline__ void mma16816(float* d, const uint32_t* a, uint32_t b0, uint32_t b1) {
    asm volatile(
        "mma.sync.aligned.m16n8k16.row.col.f32.f16.f16.f32 "
        "{%0,%1,%2,%3}, {%4,%5,%6,%7}, {%8,%9}, {%0,%1,%2,%3};"
        : "+f"(d[0]), "+f"(d[1]), "+f"(d[2]), "+f"(d[3])
        : "r"(a[0]), "r"(a[1]), "r"(a[2]), "r"(a[3]), "r"(b0), "r"(b1));
}
__device__ __forceinline__ void cp_async16(uint32_t sdst, const void* gsrc) {
    asm volatile("cp.async.cg.shared.global [%0], [%1], 16;" :: "r"(sdst), "l"(gsrc));
}
#define CP_COMMIT() asm volatile("cp.async.commit_group;" ::: "memory")
#define CP_WAIT0()  asm volatile("cp.async.wait_group 0;" ::: "memory")

// ---------------- in-register 32-pt unnormalized FHT (Sylvester) ----------------
__device__ __forceinline__ void fht32(float* v) {
#pragma unroll
    for (int s = 1; s < 32; s <<= 1) {
#pragma unroll
        for (int j = 0; j < 32; ++j) {
            if ((j & s) == 0) {
                float a = v[j], b = v[j | s];
                v[j]     = a + b;
                v[j | s] = a - b;
            }
        }
    }
}

// ---------------- kernel 1: partial sums of |w| (float4) ----------------
__global__ void k_absum(const float* __restrict__ w) {
    __shared__ float sred[256];
    int tid = threadIdx.x;
    const float4* w4 = reinterpret_cast<const float4*>(w) + blockIdx.x * 256 + tid;
    float4 v = *w4;
    sred[tid] = fabsf(v.x) + fabsf(v.y) + fabsf(v.z) + fabsf(v.w);
    __syncthreads();
#pragma unroll
    for (int off = 128; off > 0; off >>= 1) {
        if (tid < off) sred[tid] += sred[tid + off];
        __syncthreads();
    }
    if (tid == 0) g_partials[blockIdx.x] = sred[0];
}

// ---------------- kernel 2: final scale (deterministic fixed-order) ----------------
__global__ void k_scale() {
    __shared__ float sred[512];
    int tid = threadIdx.x;
    sred[tid] = g_partials[tid];
    __syncthreads();
#pragma unroll
    for (int off = 256; off > 0; off >>= 1) {
        if (tid < off) sred[tid] += sred[tid + off];
        __syncthreads();
    }
    if (tid == 0) g_scale = sred[0] / (float)WN + 1e-8f;
}

// ---------------- kernel 3: ternary quantize (float4 -> 2x half2) ----------
__global__ void k_quant(const float* __restrict__ w) {
    int idx = blockIdx.x * blockDim.x + threadIdx.x;   // 131072 threads, 4 elems each
    float inv = 1.0f / g_scale;
    float4 v = reinterpret_cast<const float4*>(w)[idx];
    float q0 = fmaxf(-1.f, fminf(1.f, rintf(v.x * inv)));
    float q1 = fmaxf(-1.f, fminf(1.f, rintf(v.y * inv)));
    float q2 = fmaxf(-1.f, fminf(1.f, rintf(v.z * inv)));
    float q3 = fmaxf(-1.f, fminf(1.f, rintf(v.w * inv)));
    __half2* dst = reinterpret_cast<__half2*>(g_wq) + idx * 2;
    dst[0] = __floats2half2_rn(q0, q1);
    dst[1] = __floats2half2_rn(q2, q3);
}

// ---------------- kernel 4: P1 — xm = FHT_g(x * alpha), fp16 out [h][t][i] --------
// 64 threads per token, 2 adjacent channels per thread; 4 tokens per 256-block.
__global__ void __launch_bounds__(256) k_p1(const float* __restrict__ x,
                                            const float* __restrict__ alpha) {
    int t  = blockIdx.x * 4 + (threadIdx.x >> 6);
    int i2 = (threadIdx.x & 63) * 2;
    const float2* xr = reinterpret_cast<const float2*>(x + (size_t)t * (G * IO) + i2);
    float v0[32], v1[32];
#pragma unroll
    for (int g = 0; g < 32; ++g) {
        float2 xv = __ldcs(&xr[g * (IO / 2)]);
        float2 av = *reinterpret_cast<const float2*>(alpha + g * IO + i2);
        v0[g] = xv.x * av.x;
        v1[g] = xv.y * av.y;
    }
    fht32(v0);
    fht32(v1);
#pragma unroll
    for (int h = 0; h < 32; ++h) {
        __half2 hv = __floats2half2_rn(v0[h], v1[h]);
        *reinterpret_cast<__half2*>(g_xm + ((size_t)h * NTOK + t) * IO + i2) = hv;
    }
}

// ---------------- kernel 5: P2 — grouped GEMM via mma.sync m16n8k16 ----------------
// grid (16, 32) = 512 CTAs (~2 waves @ 2 CTA/SM). CTA keeps its h's weight tile
// smem-resident, sweeps 4 token tiles with cp.async double-buffered A prefetch.
// Epilogue writes yp DIRECTLY from fragments (no smem staging, 1 sync per tile).
static constexpr int STR  = 136;                       // halves per smem row
static constexpr int TILE_HALVES = 128 * STR;          // 17408
static constexpr int SMEM_P2_BYTES = 3 * TILE_HALVES * 2;  // 104448 (B + A0 + A1)
static constexpr int TILES_PER_CTA = 4;

__device__ __forceinline__ void load_tile_async(const __half* __restrict__ gsrc,
                                                uint32_t sdst_base, int tid) {
#pragma unroll
    for (int it = 0; it < 8; ++it) {
        int j   = it * 256 + tid;          // 16B-chunk id, 0..2047
        int row = j >> 4;
        int c8  = (j & 15) * 8;            // starting half within row
        cp_async16(sdst_base + (uint32_t)((row * STR + c8) * 2),
                   gsrc + (size_t)row * 128 + c8);
    }
}

__global__ void __launch_bounds__(256, 2) k_p2() {
    extern __shared__ __half smem[];                   // [B | A0 | A1]
    __half* Bsm = smem;
    __half* A0  = smem + TILE_HALVES;
    const uint32_t b_base = smem_u32(Bsm);
    const uint32_t a_bases[2] = { smem_u32(A0), smem_u32(A0 + TILE_HALVES) };

    const int tid = threadIdx.x;
    const int wid = tid >> 5, lid = tid & 31;
    const int warpM = wid & 3;             // 4 M-warps of 32 rows
    const int warpN = wid >> 2;            // 2 N-warps of 64 cols
    const int h = blockIdx.y;
    const int tile0 = blockIdx.x * TILES_PER_CTA;

    const __half* Agbase = g_xm + (size_t)h * NTOK * IO;
    __half*       Ygbase = g_yp + (size_t)h * NTOK * IO;

    // prime: B tile + A tile 0
    load_tile_async(g_wq + (size_t)h * IO * IO, b_base, tid);
    load_tile_async(Agbase + (size_t)tile0 * 128 * IO, a_bases[0], tid);
    CP_COMMIT();
    CP_WAIT0();
    __syncthreads();

    // per-lane ldmatrix address components
    const int a_row = warpM * 32 + (lid & 15);                      // + mi*16
    const int a_col = (lid & 16) >> 1;                              // + k0
    const int b_row = warpN * 64 + (lid & 7) + ((lid & 16) >> 1);   // + nb*16
    const int b_col = (lid & 8);                                    // + k0

    // epilogue address components (fragment layout)
    const int e_row = warpM * 32 + (lid >> 2);                      // + mi*16 (+8)
    const int e_col = warpN * 64 + (lid & 3) * 2;                   // + ni*8

    for (int tt = 0; tt < TILES_PER_CTA; ++tt) {
        const uint32_t a_cur = a_bases[tt & 1];

        // prefetch next A tile into the other buffer
        if (tt + 1 < TILES_PER_CTA)
            load_tile_async(Agbase + (size_t)(tile0 + tt + 1) * 128 * IO,
                            a_bases[(tt + 1) & 1], tid);
        CP_COMMIT();

        float acc[2][8][4];
#pragma unroll
        for (int mi = 0; mi < 2; ++mi)
#pragma unroll
            for (int ni = 0; ni < 8; ++ni)
#pragma unroll
                for (int q = 0; q < 4; ++q) acc[mi][ni][q] = 0.f;

#pragma unroll
        for (int ks = 0; ks < 8; ++ks) {
            const int k0 = ks * 16;
            uint32_t a[2][4];
#pragma unroll
            for (int mi = 0; mi < 2; ++mi) {
                uint32_t addr = a_cur + (uint32_t)(((a_row + mi * 16) * STR + a_col + k0) * 2);
                ldsm_x4(a[mi][0], a[mi][1], a[mi][2], a[mi][3], addr);
            }
            uint32_t b[4][4];
#pragma unroll
            for (int nb = 0; nb < 4; ++nb) {
                uint32_t addr = b_base + (uint32_t)(((b_row + nb * 16) * STR + b_col + k0) * 2);
                ldsm_x4(b[nb][0], b[nb][1], b[nb][2], b[nb][3], addr);
            }
#pragma unroll
            for (int mi = 0; mi < 2; ++mi)
#pragma unroll
                for (int nb = 0; nb < 4; ++nb) {
                    mma16816(acc[mi][2 * nb],     a[mi], b[nb][0], b[nb][1]);
                    mma16816(acc[mi][2 * nb + 1], a[mi], b[nb][2], b[nb][3]);
                }
        }

        // direct epilogue: half2 stores; consecutive ni fill adjacent 16B chunks
        // of the same 8 rows -> L2 merges into full lines.
        __half* dst = Ygbase + (size_t)(tile0 + tt) * 128 * IO;
#pragma unroll
        for (int mi = 0; mi < 2; ++mi) {
            __half* drow0 = dst + (size_t)(e_row + mi * 16) * IO + e_col;
            __half* drow1 = drow0 + 8 * IO;
#pragma unroll
            for (int ni = 0; ni < 8; ++ni) {
                *reinterpret_cast<__half2*>(drow0 + ni * 8) =
                    __floats2half2_rn(acc[mi][ni][0], acc[mi][ni][1]);
                *reinterpret_cast<__half2*>(drow1 + ni * 8) =
                    __floats2half2_rn(acc[mi][ni][2], acc[mi][ni][3]);
            }
        }

        // next A tile landed + all warps done reading a_cur before it is reused
        CP_WAIT0();
        __syncthreads();
    }
}

// ---------------- kernel 6: P3 — y = FHT_h(yp) * (scale*beta/32) ----------------
// 64 threads per token, 2 adjacent outputs per thread; 4 tokens per 256-block.
__global__ void __launch_bounds__(256) k_p3(const float* __restrict__ beta,
                                            float* __restrict__ out) {
    int t  = blockIdx.x * 4 + (threadIdx.x >> 6);
    int o2 = (threadIdx.x & 63) * 2;
    const __half2* yr = reinterpret_cast<const __half2*>(g_yp + (size_t)t * IO + o2);
    float v0[32], v1[32];
#pragma unroll
    for (int h = 0; h < 32; ++h) {
        float2 f = __half22float2(__ldcs(&yr[(size_t)h * NTOK * (IO / 2)]));
        v0[h] = f.x;
        v1[h] = f.y;
    }
    fht32(v0);
    fht32(v1);
    float sc = g_scale * (1.0f / 32.0f);
#pragma unroll
    for (int g = 0; g < 32; ++g) {
        float2 bv = *reinterpret_cast<const float2*>(beta + g * IO + o2);
        float2 ov = make_float2(v0[g] * sc * bv.x, v1[g] * sc * bv.y);
        *reinterpret_cast<float2*>(out + (size_t)t * (G * IO) + g * IO + o2) = ov;
    }
}

// ---------------- launch ----------------
extern "C" void kernel_launch(void* const* d_in, const int* in_sizes, int n_in,
                              void* d_out, int out_size) {
    (void)in_sizes; (void)n_in; (void)out_size;
    const float* x     = (const float*)d_in[0];
    const float* w     = (const float*)d_in[1];
    const float* alpha = (const float*)d_in[2];
    const float* beta  = (const float*)d_in[3];
    float* out = (float*)d_out;

    k_absum<<<512, 256>>>(w);
    k_scale<<<1, 512>>>();
    k_quant<<<256, 512>>>(w);
    k_p1<<<NTOK / 4, 256>>>(x, alpha);

    cudaFuncSetAttribute(k_p2, cudaFuncAttributeMaxDynamicSharedMemorySize, SMEM_P2_BYTES);
    k_p2<<<dim3(NTOK / (128 * TILES_PER_CTA), G), 256, SMEM_P2_BYTES>>>();

    k_p3<<<NTOK / 4, 256>>>(beta, out);
}

// round 7
// speedup vs baseline: 1.0071x; 1.0071x over previous
#include <cuda_runtime.h>
#include <cuda_fp16.h>
#include <cstdint>
#include <cstddef>

// ---------------- problem constants ----------------
static constexpr int G    = 32;     // algebra dim
static constexpr int IO   = 128;    // in_o = out_o
static constexpr int NTOK = 8192;   // B*T
static constexpr int WN   = G * IO * IO;                    // 524288 weights
static constexpr size_t XM_ELEMS = (size_t)G * NTOK * IO;   // 33.5M

// ---------------- scratch (device globals: allowed) ----------------
__device__ __half g_xm[XM_ELEMS];       // [h][t][i]  fp16
__device__ __half g_yp[XM_ELEMS];       // [h][t][o]  fp16
__device__ __half g_wq[WN];             // [h][o][i]  ternary fp16 (unscaled)
__device__ float  g_partials[512];
__device__ float  g_scale;

// ---------------- PTX helpers (portable: sm_80-era, valid on compute_103) --------
__device__ __forceinline__ uint32_t smem_u32(const void* p) {
    uint32_t a;
    asm("{ .reg .u64 t; cvta.to.shared.u64 t, %1; cvt.u32.u64 %0, t; }" : "=r"(a) : "l"(p));
    return a;
}
__device__ __forceinline__ void ldsm_x4(uint32_t& r0, uint32_t& r1, uint32_t& r2, uint32_t& r3,
                                        uint32_t addr) {
    asm volatile("ldmatrix.sync.aligned.m8n8.x4.shared.b16 {%0,%1,%2,%3}, [%4];"
                 : "=r"(r0), "=r"(r1), "=r"(r2), "=r"(r3) : "r"(addr));
}
__device__ __forceinline__ void mma16816(float* d, const uint32_t* a, uint32_t b0, uint32_t b1) {
    asm volatile(
        "mma.sync.aligned.m16n8k16.row.col.f32.f16.f16.f32 "
        "{%0,%1,%2,%3}, {%4,%5,%6,%7}, {%8,%9}, {%0,%1,%2,%3};"
        : "+f"(d[0]), "+f"(d[1]), "+f"(d[2]), "+f"(d[3])
        : "r"(a[0]), "r"(a[1]), "r"(a[2]), "r"(a[3]), "r"(b0), "r"(b1));
}
__device__ __forceinline__ void cp_async16(uint32_t sdst, const void* gsrc) {
    asm volatile("cp.async.cg.shared.global [%0], [%1], 16;" :: "r"(sdst), "l"(gsrc));
}
#define CP_COMMIT() asm volatile("cp.async.commit_group;" ::: "memory")
#define CP_WAIT0()  asm volatile("cp.async.wait_group 0;" ::: "memory")

// ---------------- in-register 32-pt unnormalized FHT (Sylvester) ----------------
__device__ __forceinline__ void fht32(float* v) {
#pragma unroll
    for (int s = 1; s < 32; s <<= 1) {
#pragma unroll
        for (int j = 0; j < 32; ++j) {
            if ((j & s) == 0) {
                float a = v[j], b = v[j | s];
                v[j]     = a + b;
                v[j | s] = a - b;
            }
        }
    }
}

// ---------------- kernel 1: partial sums of |w| (float4) ----------------
__global__ void k_absum(const float* __restrict__ w) {
    __shared__ float sred[256];
    int tid = threadIdx.x;
    const float4* w4 = reinterpret_cast<const float4*>(w) + blockIdx.x * 256 + tid;
    float4 v = *w4;
    sred[tid] = fabsf(v.x) + fabsf(v.y) + fabsf(v.z) + fabsf(v.w);
    __syncthreads();
#pragma unroll
    for (int off = 128; off > 0; off >>= 1) {
        if (tid < off) sred[tid] += sred[tid + off];
        __syncthreads();
    }
    if (tid == 0) g_partials[blockIdx.x] = sred[0];
}

// ---------------- kernel 2: final scale (deterministic fixed-order) ----------------
__global__ void k_scale() {
    __shared__ float sred[512];
    int tid = threadIdx.x;
    sred[tid] = g_partials[tid];
    __syncthreads();
#pragma unroll
    for (int off = 256; off > 0; off >>= 1) {
        if (tid < off) sred[tid] += sred[tid + off];
        __syncthreads();
    }
    if (tid == 0) g_scale = sred[0] / (float)WN + 1e-8f;
}

// ---------------- kernel 3: ternary quantize (float4 -> 2x half2) ----------
__global__ void k_quant(const float* __restrict__ w) {
    int idx = blockIdx.x * blockDim.x + threadIdx.x;   // 131072 threads, 4 elems each
    float inv = 1.0f / g_scale;
    float4 v = reinterpret_cast<const float4*>(w)[idx];
    float q0 = fmaxf(-1.f, fminf(1.f, rintf(v.x * inv)));
    float q1 = fmaxf(-1.f, fminf(1.f, rintf(v.y * inv)));
    float q2 = fmaxf(-1.f, fminf(1.f, rintf(v.z * inv)));
    float q3 = fmaxf(-1.f, fminf(1.f, rintf(v.w * inv)));
    __half2* dst = reinterpret_cast<__half2*>(g_wq) + idx * 2;
    dst[0] = __floats2half2_rn(q0, q1);
    dst[1] = __floats2half2_rn(q2, q3);
}

// ---------------- kernel 4: P1 — xm = FHT_g(x * alpha), fp16 out [h][t][i] --------
// 64 threads per token, 2 adjacent channels per thread; 4 tokens per 256-block.
__global__ void __launch_bounds__(256) k_p1(const float* __restrict__ x,
                                            const float* __restrict__ alpha) {
    int t  = blockIdx.x * 4 + (threadIdx.x >> 6);
    int i2 = (threadIdx.x & 63) * 2;
    const float2* xr = reinterpret_cast<const float2*>(x + (size_t)t * (G * IO) + i2);
    float v0[32], v1[32];
#pragma unroll
    for (int g = 0; g < 32; ++g) {
        float2 xv = __ldcs(&xr[g * (IO / 2)]);
        float2 av = *reinterpret_cast<const float2*>(alpha + g * IO + i2);
        v0[g] = xv.x * av.x;
        v1[g] = xv.y * av.y;
    }
    fht32(v0);
    fht32(v1);
#pragma unroll
    for (int h = 0; h < 32; ++h) {
        __half2 hv = __floats2half2_rn(v0[h], v1[h]);
        *reinterpret_cast<__half2*>(g_xm + ((size_t)h * NTOK + t) * IO + i2) = hv;
    }
}

// ---------------- kernel 5: P2 — grouped GEMM via mma.sync m16n8k16 ----------------
// grid (16, 32) = 512 CTAs (~2 waves @ 2 CTA/SM). CTA keeps its h's weight tile
// smem-resident, sweeps 4 token tiles with cp.async double-buffered A prefetch.
// Epilogue writes yp DIRECTLY from fragments (no smem staging, 1 sync per tile).
static constexpr int STR  = 136;                       // halves per smem row
static constexpr int TILE_HALVES = 128 * STR;          // 17408
static constexpr int SMEM_P2_BYTES = 3 * TILE_HALVES * 2;  // 104448 (B + A0 + A1)
static constexpr int TILES_PER_CTA = 4;

__device__ __forceinline__ void load_tile_async(const __half* __restrict__ gsrc,
                                                uint32_t sdst_base, int tid) {
#pragma unroll
    for (int it = 0; it < 8; ++it) {
        int j   = it * 256 + tid;          // 16B-chunk id, 0..2047
        int row = j >> 4;
        int c8  = (j & 15) * 8;            // starting half within row
        cp_async16(sdst_base + (uint32_t)((row * STR + c8) * 2),
                   gsrc + (size_t)row * 128 + c8);
    }
}

__global__ void __launch_bounds__(256, 2) k_p2() {
    extern __shared__ __half smem[];                   // [B | A0 | A1]
    __half* Bsm = smem;
    __half* A0  = smem + TILE_HALVES;
    const uint32_t b_base = smem_u32(Bsm);
    const uint32_t a_bases[2] = { smem_u32(A0), smem_u32(A0 + TILE_HALVES) };

    const int tid = threadIdx.x;
    const int wid = tid >> 5, lid = tid & 31;
    const int warpM = wid & 3;             // 4 M-warps of 32 rows
    const int warpN = wid >> 2;            // 2 N-warps of 64 cols
    const int h = blockIdx.y;
    const int tile0 = blockIdx.x * TILES_PER_CTA;

    const __half* Agbase = g_xm + (size_t)h * NTOK * IO;
    __half*       Ygbase = g_yp + (size_t)h * NTOK * IO;

    // prime: B tile + A tile 0
    load_tile_async(g_wq + (size_t)h * IO * IO, b_base, tid);
    load_tile_async(Agbase + (size_t)tile0 * 128 * IO, a_bases[0], tid);
    CP_COMMIT();
    CP_WAIT0();
    __syncthreads();

    // per-lane ldmatrix address components
    const int a_row = warpM * 32 + (lid & 15);                      // + mi*16
    const int a_col = (lid & 16) >> 1;                              // + k0
    const int b_row = warpN * 64 + (lid & 7) + ((lid & 16) >> 1);   // + nb*16
    const int b_col = (lid & 8);                                    // + k0

    // epilogue address components (fragment layout)
    const int e_row = warpM * 32 + (lid >> 2);                      // + mi*16 (+8)
    const int e_col = warpN * 64 + (lid & 3) * 2;                   // + ni*8

    for (int tt = 0; tt < TILES_PER_CTA; ++tt) {
        const uint32_t a_cur = a_bases[tt & 1];

        // prefetch next A tile into the other buffer
        if (tt + 1 < TILES_PER_CTA)
            load_tile_async(Agbase + (size_t)(tile0 + tt + 1) * 128 * IO,
                            a_bases[(tt + 1) & 1], tid);
        CP_COMMIT();

        float acc[2][8][4];
#pragma unroll
        for (int mi = 0; mi < 2; ++mi)
#pragma unroll
            for (int ni = 0; ni < 8; ++ni)
#pragma unroll
                for (int q = 0; q < 4; ++q) acc[mi][ni][q] = 0.f;

#pragma unroll
        for (int ks = 0; ks < 8; ++ks) {
            const int k0 = ks * 16;
            uint32_t a[2][4];
#pragma unroll
            for (int mi = 0; mi < 2; ++mi) {
                uint32_t addr = a_cur + (uint32_t)(((a_row + mi * 16) * STR + a_col + k0) * 2);
                ldsm_x4(a[mi][0], a[mi][1], a[mi][2], a[mi][3], addr);
            }
            uint32_t b[4][4];
#pragma unroll
            for (int nb = 0; nb < 4; ++nb) {
                uint32_t addr = b_base + (uint32_t)(((b_row + nb * 16) * STR + b_col + k0) * 2);
                ldsm_x4(b[nb][0], b[nb][1], b[nb][2], b[nb][3], addr);
            }
#pragma unroll
            for (int mi = 0; mi < 2; ++mi)
#pragma unroll
                for (int nb = 0; nb < 4; ++nb) {
                    mma16816(acc[mi][2 * nb],     a[mi], b[nb][0], b[nb][1]);
                    mma16816(acc[mi][2 * nb + 1], a[mi], b[nb][2], b[nb][3]);
                }
        }

        // direct epilogue: half2 stores; consecutive ni fill adjacent 16B chunks
        // of the same 8 rows -> L2 merges into full lines.
        __half* dst = Ygbase + (size_t)(tile0 + tt) * 128 * IO;
#pragma unroll
        for (int mi = 0; mi < 2; ++mi) {
            __half* drow0 = dst + (size_t)(e_row + mi * 16) * IO + e_col;
            __half* drow1 = drow0 + 8 * IO;
#pragma unroll
            for (int ni = 0; ni < 8; ++ni) {
                *reinterpret_cast<__half2*>(drow0 + ni * 8) =
                    __floats2half2_rn(acc[mi][ni][0], acc[mi][ni][1]);
                *reinterpret_cast<__half2*>(drow1 + ni * 8) =
                    __floats2half2_rn(acc[mi][ni][2], acc[mi][ni][3]);
            }
        }

        // next A tile landed + all warps done reading a_cur before it is reused
        CP_WAIT0();
        __syncthreads();
    }
}

// ---------------- kernel 6: P3 — y = FHT_h(yp) * (scale*beta/32) ----------------
// 64 threads per token, 2 adjacent outputs per thread; 4 tokens per 256-block.
__global__ void __launch_bounds__(256) k_p3(const float* __restrict__ beta,
                                            float* __restrict__ out) {
    int t  = blockIdx.x * 4 + (threadIdx.x >> 6);
    int o2 = (threadIdx.x & 63) * 2;
    const __half2* yr = reinterpret_cast<const __half2*>(g_yp + (size_t)t * IO + o2);
    float v0[32], v1[32];
#pragma unroll
    for (int h = 0; h < 32; ++h) {
        float2 f = __half22float2(__ldcs(&yr[(size_t)h * NTOK * (IO / 2)]));
        v0[h] = f.x;
        v1[h] = f.y;
    }
    fht32(v0);
    fht32(v1);
    float sc = g_scale * (1.0f / 32.0f);
#pragma unroll
    for (int g = 0; g < 32; ++g) {
        float2 bv = *reinterpret_cast<const float2*>(beta + g * IO + o2);
        float2 ov = make_float2(v0[g] * sc * bv.x, v1[g] * sc * bv.y);
        *reinterpret_cast<float2*>(out + (size_t)t * (G * IO) + g * IO + o2) = ov;
    }
}

// ---------------- launch ----------------
extern "C" void kernel_launch(void* const* d_in, const int* in_sizes, int n_in,
                              void* d_out, int out_size) {
    (void)in_sizes; (void)n_in; (void)out_size;
    const float* x     = (const float*)d_in[0];
    const float* w     = (const float*)d_in[1];
    const float* alpha = (const float*)d_in[2];
    const float* beta  = (const float*)d_in[3];
    float* out = (float*)d_out;

    k_absum<<<512, 256>>>(w);
    k_scale<<<1, 512>>>();
    k_quant<<<256, 512>>>(w);
    k_p1<<<NTOK / 4, 256>>>(x, alpha);

    cudaFuncSetAttribute(k_p2, cudaFuncAttributeMaxDynamicSharedMemorySize, SMEM_P2_BYTES);
    k_p2<<<dim3(NTOK / (128 * TILES_PER_CTA), G), 256, SMEM_P2_BYTES>>>();

    k_p3<<<NTOK / 4, 256>>>(beta, out);
}

// round 11
// speedup vs baseline: 1.0540x; 1.0465x over previous
#include <cuda_runtime.h>
#include <cuda_fp16.h>
#include <cstdint>
#include <cstddef>

// ---------------- problem constants ----------------
static constexpr int G    = 32;     // algebra dim
static constexpr int IO   = 128;    // in_o = out_o
static constexpr int NTOK = 8192;   // B*T
static constexpr int WN   = G * IO * IO;                    // 524288 weights
static constexpr size_t XM_ELEMS = (size_t)G * NTOK * IO;   // 33.5M

// ---------------- scratch (device globals: allowed) ----------------
__device__ __half g_xm[XM_ELEMS];       // [h][t][i]  fp16
__device__ __half g_yp[XM_ELEMS];       // [h][t][o]  fp16
__device__ __half g_wq[WN];             // [h][o][i]  ternary fp16 (unscaled)
__device__ float  g_partials[512];
__device__ float  g_scale;

// ---------------- PTX helpers (portable: sm_80-era, valid on compute_103) --------
__device__ __forceinline__ uint32_t smem_u32(const void* p) {
    uint32_t a;
    asm("{ .reg .u64 t; cvta.to.shared.u64 t, %1; cvt.u32.u64 %0, t; }" : "=r"(a) : "l"(p));
    return a;
}
__device__ __forceinline__ void ldsm_x4(uint32_t& r0, uint32_t& r1, uint32_t& r2, uint32_t& r3,
                                        uint32_t addr) {
    asm volatile("ldmatrix.sync.aligned.m8n8.x4.shared.b16 {%0,%1,%2,%3}, [%4];"
                 : "=r"(r0), "=r"(r1), "=r"(r2), "=r"(r3) : "r"(addr));
}
__device__ __forceinline__ void mma16816(float* d, const uint32_t* a, uint32_t b0, uint32_t b1) {
    asm volatile(
        "mma.sync.aligned.m16n8k16.row.col.f32.f16.f16.f32 "
        "{%0,%1,%2,%3}, {%4,%5,%6,%7}, {%8,%9}, {%0,%1,%2,%3};"
        : "+f"(d[0]), "+f"(d[1]), "+f"(d[2]), "+f"(d[3])
        : "r"(a[0]), "r"(a[1]), "r"(a[2]), "r"(a[3]), "r"(b0), "r"(b1));
}
__device__ __forceinline__ void cp_async16(uint32_t sdst, const void* gsrc) {
    asm volatile("cp.async.cg.shared.global [%0], [%1], 16;" :: "r"(sdst), "l"(gsrc));
}
#define CP_COMMIT() asm volatile("cp.async.commit_group;" ::: "memory")
#define CP_WAIT0()  asm volatile("cp.async.wait_group 0;" ::: "memory")

// ---------------- in-register 32-pt unnormalized FHT (Sylvester) ----------------
__device__ __forceinline__ void fht32(float* v) {
#pragma unroll
    for (int s = 1; s < 32; s <<= 1) {
#pragma unroll
        for (int j = 0; j < 32; ++j) {
            if ((j & s) == 0) {
                float a = v[j], b = v[j | s];
                v[j]     = a + b;
                v[j | s] = a - b;
            }
        }
    }
}

// ---------------- kernel 1: partial sums of |w| (float4) ----------------
__global__ void k_absum(const float* __restrict__ w) {
    __shared__ float sred[256];
    int tid = threadIdx.x;
    const float4* w4 = reinterpret_cast<const float4*>(w) + blockIdx.x * 256 + tid;
    float4 v = *w4;
    sred[tid] = fabsf(v.x) + fabsf(v.y) + fabsf(v.z) + fabsf(v.w);
    __syncthreads();
#pragma unroll
    for (int off = 128; off > 0; off >>= 1) {
        if (tid < off) sred[tid] += sred[tid + off];
        __syncthreads();
    }
    if (tid == 0) g_partials[blockIdx.x] = sred[0];
}

// ---------------- kernel 2: final scale (deterministic fixed-order) ----------------
__global__ void k_scale() {
    __shared__ float sred[512];
    int tid = threadIdx.x;
    sred[tid] = g_partials[tid];
    __syncthreads();
#pragma unroll
    for (int off = 256; off > 0; off >>= 1) {
        if (tid < off) sred[tid] += sred[tid + off];
        __syncthreads();
    }
    if (tid == 0) g_scale = sred[0] / (float)WN + 1e-8f;
}

// ---------------- kernel 3: ternary quantize (float4 -> 2x half2) ----------
__global__ void k_quant(const float* __restrict__ w) {
    int idx = blockIdx.x * blockDim.x + threadIdx.x;   // 131072 threads, 4 elems each
    float inv = 1.0f / g_scale;
    float4 v = reinterpret_cast<const float4*>(w)[idx];
    float q0 = fmaxf(-1.f, fminf(1.f, rintf(v.x * inv)));
    float q1 = fmaxf(-1.f, fminf(1.f, rintf(v.y * inv)));
    float q2 = fmaxf(-1.f, fminf(1.f, rintf(v.z * inv)));
    float q3 = fmaxf(-1.f, fminf(1.f, rintf(v.w * inv)));
    __half2* dst = reinterpret_cast<__half2*>(g_wq) + idx * 2;
    dst[0] = __floats2half2_rn(q0, q1);
    dst[1] = __floats2half2_rn(q2, q3);
}

// ---------------- kernel 4: P1 — xm = FHT_g(x * alpha), fp16 out [h][t][i] --------
// 64 threads per token, 2 adjacent channels per thread; 4 tokens per 256-block.
__global__ void __launch_bounds__(256) k_p1(const float* __restrict__ x,
                                            const float* __restrict__ alpha) {
    int t  = blockIdx.x * 4 + (threadIdx.x >> 6);
    int i2 = (threadIdx.x & 63) * 2;
    const float2* xr = reinterpret_cast<const float2*>(x + (size_t)t * (G * IO) + i2);
    float v0[32], v1[32];
#pragma unroll
    for (int g = 0; g < 32; ++g) {
        float2 xv = __ldcs(&xr[g * (IO / 2)]);
        float2 av = *reinterpret_cast<const float2*>(alpha + g * IO + i2);
        v0[g] = xv.x * av.x;
        v1[g] = xv.y * av.y;
    }
    fht32(v0);
    fht32(v1);
#pragma unroll
    for (int h = 0; h < 32; ++h) {
        __half2 hv = __floats2half2_rn(v0[h], v1[h]);
        *reinterpret_cast<__half2*>(g_xm + ((size_t)h * NTOK + t) * IO + i2) = hv;
    }
}

// ---------------- kernel 5: P2 — grouped GEMM via mma.sync m16n8k16 ----------------
// grid (8, 32) = 256 CTAs = ONE wave @ 2 CTA/SM (load-bearing: do not change).
// CTA keeps its h's weight tile smem-resident, sweeps 8 token tiles with
// cp.async double-buffered A prefetch. Epilogue: each warp stages its fragments
// into a_cur (conflict-free) and writes back ONLY its own 32x64 region ->
// 2 block barriers per tile instead of 3.
static constexpr int STR  = 136;                       // halves per smem row
static constexpr int TILE_HALVES = 128 * STR;          // 17408
static constexpr int SMEM_P2_BYTES = 3 * TILE_HALVES * 2;  // 104448 (B + A0 + A1)
static constexpr int TILES_PER_CTA = 8;

__device__ __forceinline__ void load_tile_async(const __half* __restrict__ gsrc,
                                                uint32_t sdst_base, int tid) {
#pragma unroll
    for (int it = 0; it < 8; ++it) {
        int j   = it * 256 + tid;          // 16B-chunk id, 0..2047
        int row = j >> 4;
        int c8  = (j & 15) * 8;            // starting half within row
        cp_async16(sdst_base + (uint32_t)((row * STR + c8) * 2),
                   gsrc + (size_t)row * 128 + c8);
    }
}

__global__ void __launch_bounds__(256, 2) k_p2() {
    extern __shared__ __half smem[];                   // [B | A0 | A1]
    __half* Bsm = smem;
    __half* A0  = smem + TILE_HALVES;
    const uint32_t b_base = smem_u32(Bsm);
    const uint32_t a_bases[2] = { smem_u32(A0), smem_u32(A0 + TILE_HALVES) };

    const int tid = threadIdx.x;
    const int wid = tid >> 5, lid = tid & 31;
    const int warpM = wid & 3;             // 4 M-warps of 32 rows
    const int warpN = wid >> 2;            // 2 N-warps of 64 cols
    const int h = blockIdx.y;
    const int tile0 = blockIdx.x * TILES_PER_CTA;

    const __half* Agbase = g_xm + (size_t)h * NTOK * IO;
    __half*       Ygbase = g_yp + (size_t)h * NTOK * IO;

    // prime: B tile + A tile 0
    load_tile_async(g_wq + (size_t)h * IO * IO, b_base, tid);
    load_tile_async(Agbase + (size_t)tile0 * 128 * IO, a_bases[0], tid);
    CP_COMMIT();
    CP_WAIT0();
    __syncthreads();

    // per-lane ldmatrix address components
    const int a_row = warpM * 32 + (lid & 15);                      // + mi*16
    const int a_col = (lid & 16) >> 1;                              // + k0
    const int b_row = warpN * 64 + (lid & 7) + ((lid & 16) >> 1);   // + nb*16
    const int b_col = (lid & 8);                                    // + k0

    // epilogue components
    const int e_row = warpM * 32 + (lid >> 2);                      // + mi*16 (+8)
    const int e_col = warpN * 64 + (lid & 3) * 2;                   // + ni*8

    for (int tt = 0; tt < TILES_PER_CTA; ++tt) {
        const uint32_t a_cur = a_bases[tt & 1];
        __half* Astage = (tt & 1) ? (A0 + TILE_HALVES) : A0;

        // prefetch next A tile into the other buffer
        if (tt + 1 < TILES_PER_CTA)
            load_tile_async(Agbase + (size_t)(tile0 + tt + 1) * 128 * IO,
                            a_bases[(tt + 1) & 1], tid);
        CP_COMMIT();

        float acc[2][8][4];
#pragma unroll
        for (int mi = 0; mi < 2; ++mi)
#pragma unroll
            for (int ni = 0; ni < 8; ++ni)
#pragma unroll
                for (int q = 0; q < 4; ++q) acc[mi][ni][q] = 0.f;

#pragma unroll
        for (int ks = 0; ks < 8; ++ks) {
            const int k0 = ks * 16;
            uint32_t a[2][4];
#pragma unroll
            for (int mi = 0; mi < 2; ++mi) {
                uint32_t addr = a_cur + (uint32_t)(((a_row + mi * 16) * STR + a_col + k0) * 2);
                ldsm_x4(a[mi][0], a[mi][1], a[mi][2], a[mi][3], addr);
            }
            uint32_t b[4][4];
#pragma unroll
            for (int nb = 0; nb < 4; ++nb) {
                uint32_t addr = b_base + (uint32_t)(((b_row + nb * 16) * STR + b_col + k0) * 2);
                ldsm_x4(b[nb][0], b[nb][1], b[nb][2], b[nb][3], addr);
            }
#pragma unroll
            for (int mi = 0; mi < 2; ++mi)
#pragma unroll
                for (int nb = 0; nb < 4; ++nb) {
                    mma16816(acc[mi][2 * nb],     a[mi], b[nb][0], b[nb][1]);
                    mma16816(acc[mi][2 * nb + 1], a[mi], b[nb][2], b[nb][3]);
                }
        }

        __syncthreads();   // barrier 1: everyone done ldsm from a_cur

        // stage this warp's fragments into a_cur (bank-conflict-free pattern)
#pragma unroll
        for (int mi = 0; mi < 2; ++mi)
#pragma unroll
            for (int ni = 0; ni < 8; ++ni) {
                int row = e_row + mi * 16;
                int col = e_col + ni * 8;
                *reinterpret_cast<__half2*>(Astage + row * STR + col) =
                    __floats2half2_rn(acc[mi][ni][0], acc[mi][ni][1]);
                *reinterpret_cast<__half2*>(Astage + (row + 8) * STR + col) =
                    __floats2half2_rn(acc[mi][ni][2], acc[mi][ni][3]);
            }
        __syncwarp();      // warp-local: this warp reads back only its own region

        // write back own 32x64 region: rows warpM*32..+32, cols warpN*64..+64
        {
            __half* dst = Ygbase + (size_t)(tile0 + tt) * 128 * IO;
#pragma unroll
            for (int it = 0; it < 8; ++it) {
                int row = warpM * 32 + it * 4 + (lid >> 3);
                int c8  = warpN * 64 + (lid & 7) * 8;
                uint4 val = *reinterpret_cast<const uint4*>(Astage + row * STR + c8);
                *reinterpret_cast<uint4*>(dst + (size_t)row * 128 + c8) = val;
            }
        }

        // barrier 2: next A tile landed, and nobody still reading a_cur stage
        CP_WAIT0();
        __syncthreads();
    }
}

// ---------------- kernel 6: P3 — y = FHT_h(yp) * (scale*beta/32) ----------------
// 64 threads per token, 2 adjacent outputs per thread; 4 tokens per 256-block.
__global__ void __launch_bounds__(256) k_p3(const float* __restrict__ beta,
                                            float* __restrict__ out) {
    int t  = blockIdx.x * 4 + (threadIdx.x >> 6);
    int o2 = (threadIdx.x & 63) * 2;
    const __half2* yr = reinterpret_cast<const __half2*>(g_yp + (size_t)t * IO + o2);
    float v0[32], v1[32];
#pragma unroll
    for (int h = 0; h < 32; ++h) {
        float2 f = __half22float2(__ldcs(&yr[(size_t)h * NTOK * (IO / 2)]));
        v0[h] = f.x;
        v1[h] = f.y;
    }
    fht32(v0);
    fht32(v1);
    float sc = g_scale * (1.0f / 32.0f);
#pragma unroll
    for (int g = 0; g < 32; ++g) {
        float2 bv = *reinterpret_cast<const float2*>(beta + g * IO + o2);
        float2 ov = make_float2(v0[g] * sc * bv.x, v1[g] * sc * bv.y);
        *reinterpret_cast<float2*>(out + (size_t)t * (G * IO) + g * IO + o2) = ov;
    }
}

// ---------------- launch ----------------
extern "C" void kernel_launch(void* const* d_in, const int* in_sizes, int n_in,
                              void* d_out, int out_size) {
    (void)in_sizes; (void)n_in; (void)out_size;
    const float* x     = (const float*)d_in[0];
    const float* w     = (const float*)d_in[1];
    const float* alpha = (const float*)d_in[2];
    const float* beta  = (const float*)d_in[3];
    float* out = (float*)d_out;

    k_absum<<<512, 256>>>(w);
    k_scale<<<1, 512>>>();
    k_quant<<<256, 512>>>(w);
    k_p1<<<NTOK / 4, 256>>>(x, alpha);

    cudaFuncSetAttribute(k_p2, cudaFuncAttributeMaxDynamicSharedMemorySize, SMEM_P2_BYTES);
    k_p2<<<dim3(NTOK / (128 * TILES_PER_CTA), G), 256, SMEM_P2_BYTES>>>();

    k_p3<<<NTOK / 4, 256>>>(beta, out);
}

// round 12
// speedup vs baseline: 1.0878x; 1.0321x over previous
#include <cuda_runtime.h>
#include <cuda_fp16.h>
#include <cstdint>
#include <cstddef>

// ---------------- problem constants ----------------
static constexpr int G    = 32;     // algebra dim
static constexpr int IO   = 128;    // in_o = out_o
static constexpr int NTOK = 8192;   // B*T
static constexpr int WN   = G * IO * IO;                    // 524288 weights
static constexpr size_t XM_ELEMS = (size_t)G * NTOK * IO;   // 33.5M
static constexpr int NJOBS = (NTOK / 128) * G;              // 2048 jobs (h, tile)
static constexpr int P2_CTAS = 296;                         // 148 SMs x 2 slots

// ---------------- scratch (device globals: allowed) ----------------
__device__ __half g_xm[XM_ELEMS];       // [h][t][i]  fp16
__device__ __half g_yp[XM_ELEMS];       // [h][t][o]  fp16
__device__ __half g_wq[WN];             // [h][o][i]  ternary fp16 (unscaled)
__device__ float  g_partials[128];
__device__ float  g_scale;

// ---------------- PTX helpers (portable: sm_80-era, valid on compute_103) --------
__device__ __forceinline__ uint32_t smem_u32(const void* p) {
    uint32_t a;
    asm("{ .reg .u64 t; cvta.to.shared.u64 t, %1; cvt.u32.u64 %0, t; }" : "=r"(a) : "l"(p));
    return a;
}
__device__ __forceinline__ void ldsm_x4(uint32_t& r0, uint32_t& r1, uint32_t& r2, uint32_t& r3,
                                        uint32_t addr) {
    asm volatile("ldmatrix.sync.aligned.m8n8.x4.shared.b16 {%0,%1,%2,%3}, [%4];"
                 : "=r"(r0), "=r"(r1), "=r"(r2), "=r"(r3) : "r"(addr));
}
__device__ __forceinline__ void mma16816(float* d, const uint32_t* a, uint32_t b0, uint32_t b1) {
    asm volatile(
        "mma.sync.aligned.m16n8k16.row.col.f32.f16.f16.f32 "
        "{%0,%1,%2,%3}, {%4,%5,%6,%7}, {%8,%9}, {%0,%1,%2,%3};"
        : "+f"(d[0]), "+f"(d[1]), "+f"(d[2]), "+f"(d[3])
        : "r"(a[0]), "r"(a[1]), "r"(a[2]), "r"(a[3]), "r"(b0), "r"(b1));
}
__device__ __forceinline__ void cp_async16(uint32_t sdst, const void* gsrc) {
    asm volatile("cp.async.cg.shared.global [%0], [%1], 16;" :: "r"(sdst), "l"(gsrc));
}
#define CP_COMMIT() asm volatile("cp.async.commit_group;" ::: "memory")
#define CP_WAIT0()  asm volatile("cp.async.wait_group 0;" ::: "memory")

// ---------------- in-register 32-pt unnormalized FHT (Sylvester) ----------------
__device__ __forceinline__ void fht32(float* v) {
#pragma unroll
    for (int s = 1; s < 32; s <<= 1) {
#pragma unroll
        for (int j = 0; j < 32; ++j) {
            if ((j & s) == 0) {
                float a = v[j], b = v[j | s];
                v[j]     = a + b;
                v[j | s] = a - b;
            }
        }
    }
}

// ---------------- kernel 1: partial sums of |w| (float4, 128 blocks) -------------
__global__ void k_absum(const float* __restrict__ w) {
    __shared__ float sred[256];
    int tid = threadIdx.x;
    const float4* w4 = reinterpret_cast<const float4*>(w) + blockIdx.x * 1024 + tid;
    float s = 0.f;
#pragma unroll
    for (int k = 0; k < 4; ++k) {
        float4 v = w4[k * 256];
        s += fabsf(v.x) + fabsf(v.y) + fabsf(v.z) + fabsf(v.w);
    }
    sred[tid] = s;
    __syncthreads();
#pragma unroll
    for (int off = 128; off > 0; off >>= 1) {
        if (tid < off) sred[tid] += sred[tid + off];
        __syncthreads();
    }
    if (tid == 0) g_partials[blockIdx.x] = sred[0];
}

// ---------------- kernel 2: ternary quantize (scale computed inline) -------------
__global__ void k_quant(const float* __restrict__ w) {
    __shared__ float sscale;
    int tid = threadIdx.x;
    if (tid == 0) {
        float s = 0.f;
#pragma unroll
        for (int i = 0; i < 128; ++i) s += g_partials[i];   // fixed order: deterministic
        sscale = s / (float)WN + 1e-8f;
        if (blockIdx.x == 0) g_scale = sscale;
    }
    __syncthreads();
    float inv = 1.0f / sscale;
    int idx = blockIdx.x * blockDim.x + tid;   // 131072 threads, 4 elems each
    float4 v = reinterpret_cast<const float4*>(w)[idx];
    float q0 = fmaxf(-1.f, fminf(1.f, rintf(v.x * inv)));
    float q1 = fmaxf(-1.f, fminf(1.f, rintf(v.y * inv)));
    float q2 = fmaxf(-1.f, fminf(1.f, rintf(v.z * inv)));
    float q3 = fmaxf(-1.f, fminf(1.f, rintf(v.w * inv)));
    __half2* dst = reinterpret_cast<__half2*>(g_wq) + idx * 2;
    dst[0] = __floats2half2_rn(q0, q1);
    dst[1] = __floats2half2_rn(q2, q3);
}

// ---------------- kernel 4: P1 — xm = FHT_g(x * alpha), fp16 out [h][t][i] --------
// 64 threads per token, 2 adjacent channels per thread; 4 tokens per 256-block.
__global__ void __launch_bounds__(256) k_p1(const float* __restrict__ x,
                                            const float* __restrict__ alpha) {
    int t  = blockIdx.x * 4 + (threadIdx.x >> 6);
    int i2 = (threadIdx.x & 63) * 2;
    const float2* xr = reinterpret_cast<const float2*>(x + (size_t)t * (G * IO) + i2);
    float v0[32], v1[32];
#pragma unroll
    for (int g = 0; g < 32; ++g) {
        float2 xv = __ldcs(&xr[g * (IO / 2)]);
        float2 av = *reinterpret_cast<const float2*>(alpha + g * IO + i2);
        v0[g] = xv.x * av.x;
        v1[g] = xv.y * av.y;
    }
    fht32(v0);
    fht32(v1);
#pragma unroll
    for (int h = 0; h < 32; ++h) {
        __half2 hv = __floats2half2_rn(v0[h], v1[h]);
        *reinterpret_cast<__half2*>(g_xm + ((size_t)h * NTOK + t) * IO + i2) = hv;
    }
}

// ---------------- kernel 5: P2 — grouped GEMM via mma.sync m16n8k16 ----------------
// Job-balanced persistent grid: 2048 jobs (h-major), 296 CTAs = 148 SMs x 2 slots.
// CTA c handles jobs [c*2048/296, (c+1)*2048/296) — ~6.92 jobs, crossing an h
// boundary at most once (one extra B reload). cp.async double-buffered A prefetch;
// warp-private staged epilogue (2 block barriers/tile).
static constexpr int STR  = 136;                       // halves per smem row
static constexpr int TILE_HALVES = 128 * STR;          // 17408
static constexpr int SMEM_P2_BYTES = 3 * TILE_HALVES * 2;  // 104448 (B + A0 + A1)

__device__ __forceinline__ void load_tile_async(const __half* __restrict__ gsrc,
                                                uint32_t sdst_base, int tid) {
#pragma unroll
    for (int it = 0; it < 8; ++it) {
        int j   = it * 256 + tid;          // 16B-chunk id, 0..2047
        int row = j >> 4;
        int c8  = (j & 15) * 8;            // starting half within row
        cp_async16(sdst_base + (uint32_t)((row * STR + c8) * 2),
                   gsrc + (size_t)row * 128 + c8);
    }
}

__global__ void __launch_bounds__(256, 2) k_p2() {
    extern __shared__ __half smem[];                   // [B | A0 | A1]
    __half* Bsm = smem;
    __half* A0  = smem + TILE_HALVES;
    const uint32_t b_base = smem_u32(Bsm);
    const uint32_t a_bases[2] = { smem_u32(A0), smem_u32(A0 + TILE_HALVES) };

    const int tid = threadIdx.x;
    const int wid = tid >> 5, lid = tid & 31;
    const int warpM = wid & 3;             // 4 M-warps of 32 rows
    const int warpN = wid >> 2;            // 2 N-warps of 64 cols
    const int c  = blockIdx.x;
    const int j0 = (c * NJOBS) / P2_CTAS;
    const int j1 = ((c + 1) * NJOBS) / P2_CTAS;

    // prime: B for h(j0) + A for job j0
    int cur_h = j0 >> 6;
    load_tile_async(g_wq + (size_t)cur_h * IO * IO, b_base, tid);
    load_tile_async(g_xm + ((size_t)cur_h * NTOK + (size_t)(j0 & 63) * 128) * IO,
                    a_bases[j0 & 1], tid);
    CP_COMMIT();
    CP_WAIT0();
    __syncthreads();

    // per-lane ldmatrix address components
    const int a_row = warpM * 32 + (lid & 15);                      // + mi*16
    const int a_col = (lid & 16) >> 1;                              // + k0
    const int b_row = warpN * 64 + (lid & 7) + ((lid & 16) >> 1);   // + nb*16
    const int b_col = (lid & 8);                                    // + k0

    // epilogue components
    const int e_row = warpM * 32 + (lid >> 2);                      // + mi*16 (+8)
    const int e_col = warpN * 64 + (lid & 3) * 2;                   // + ni*8

    for (int j = j0; j < j1; ++j) {
        const int h    = j >> 6;
        const int tile = j & 63;

        if (h != cur_h) {   // at most once per CTA
            load_tile_async(g_wq + (size_t)h * IO * IO, b_base, tid);
            CP_COMMIT();
            CP_WAIT0();
            __syncthreads();
            cur_h = h;
        }

        const uint32_t a_cur = a_bases[j & 1];
        __half* Astage = (j & 1) ? (A0 + TILE_HALVES) : A0;

        // prefetch next job's A tile into the other buffer
        if (j + 1 < j1) {
            int jn = j + 1;
            load_tile_async(g_xm + ((size_t)(jn >> 6) * NTOK + (size_t)(jn & 63) * 128) * IO,
                            a_bases[jn & 1], tid);
        }
        CP_COMMIT();

        float acc[2][8][4];
#pragma unroll
        for (int mi = 0; mi < 2; ++mi)
#pragma unroll
            for (int ni = 0; ni < 8; ++ni)
#pragma unroll
                for (int q = 0; q < 4; ++q) acc[mi][ni][q] = 0.f;

#pragma unroll
        for (int ks = 0; ks < 8; ++ks) {
            const int k0 = ks * 16;
            uint32_t a[2][4];
#pragma unroll
            for (int mi = 0; mi < 2; ++mi) {
                uint32_t addr = a_cur + (uint32_t)(((a_row + mi * 16) * STR + a_col + k0) * 2);
                ldsm_x4(a[mi][0], a[mi][1], a[mi][2], a[mi][3], addr);
            }
            uint32_t b[4][4];
#pragma unroll
            for (int nb = 0; nb < 4; ++nb) {
                uint32_t addr = b_base + (uint32_t)(((b_row + nb * 16) * STR + b_col + k0) * 2);
                ldsm_x4(b[nb][0], b[nb][1], b[nb][2], b[nb][3], addr);
            }
#pragma unroll
            for (int mi = 0; mi < 2; ++mi)
#pragma unroll
                for (int nb = 0; nb < 4; ++nb) {
                    mma16816(acc[mi][2 * nb],     a[mi], b[nb][0], b[nb][1]);
                    mma16816(acc[mi][2 * nb + 1], a[mi], b[nb][2], b[nb][3]);
                }
        }

        __syncthreads();   // barrier 1: everyone done ldsm from a_cur

        // stage this warp's fragments into a_cur (bank-conflict-free pattern)
#pragma unroll
        for (int mi = 0; mi < 2; ++mi)
#pragma unroll
            for (int ni = 0; ni < 8; ++ni) {
                int row = e_row + mi * 16;
                int col = e_col + ni * 8;
                *reinterpret_cast<__half2*>(Astage + row * STR + col) =
                    __floats2half2_rn(acc[mi][ni][0], acc[mi][ni][1]);
                *reinterpret_cast<__half2*>(Astage + (row + 8) * STR + col) =
                    __floats2half2_rn(acc[mi][ni][2], acc[mi][ni][3]);
            }
        __syncwarp();      // warp-local: this warp reads back only its own region

        // write back own 32x64 region: rows warpM*32..+32, cols warpN*64..+64
        {
            __half* dst = g_yp + ((size_t)h * NTOK + (size_t)tile * 128) * IO;
#pragma unroll
            for (int it = 0; it < 8; ++it) {
                int row = warpM * 32 + it * 4 + (lid >> 3);
                int c8  = warpN * 64 + (lid & 7) * 8;
                uint4 val = *reinterpret_cast<const uint4*>(Astage + row * STR + c8);
                *reinterpret_cast<uint4*>(dst + (size_t)row * 128 + c8) = val;
            }
        }

        // barrier 2: next A tile landed, and nobody still reading a_cur stage
        CP_WAIT0();
        __syncthreads();
    }
}

// ---------------- kernel 6: P3 — y = FHT_h(yp) * (scale*beta/32) ----------------
// 64 threads per token, 2 adjacent outputs per thread; 4 tokens per 256-block.
__global__ void __launch_bounds__(256) k_p3(const float* __restrict__ beta,
                                            float* __restrict__ out) {
    int t  = blockIdx.x * 4 + (threadIdx.x >> 6);
    int o2 = (threadIdx.x & 63) * 2;
    const __half2* yr = reinterpret_cast<const __half2*>(g_yp + (size_t)t * IO + o2);
    float v0[32], v1[32];
#pragma unroll
    for (int h = 0; h < 32; ++h) {
        float2 f = __half22float2(__ldcs(&yr[(size_t)h * NTOK * (IO / 2)]));
        v0[h] = f.x;
        v1[h] = f.y;
    }
    fht32(v0);
    fht32(v1);
    float sc = g_scale * (1.0f / 32.0f);
#pragma unroll
    for (int g = 0; g < 32; ++g) {
        float2 bv = *reinterpret_cast<const float2*>(beta + g * IO + o2);
        float2 ov = make_float2(v0[g] * sc * bv.x, v1[g] * sc * bv.y);
        *reinterpret_cast<float2*>(out + (size_t)t * (G * IO) + g * IO + o2) = ov;
    }
}

// ---------------- launch ----------------
extern "C" void kernel_launch(void* const* d_in, const int* in_sizes, int n_in,
                              void* d_out, int out_size) {
    (void)in_sizes; (void)n_in; (void)out_size;
    const float* x     = (const float*)d_in[0];
    const float* w     = (const float*)d_in[1];
    const float* alpha = (const float*)d_in[2];
    const float* beta  = (const float*)d_in[3];
    float* out = (float*)d_out;

    k_absum<<<128, 256>>>(w);
    k_quant<<<256, 512>>>(w);
    k_p1<<<NTOK / 4, 256>>>(x, alpha);

    cudaFuncSetAttribute(k_p2, cudaFuncAttributeMaxDynamicSharedMemorySize, SMEM_P2_BYTES);
    k_p2<<<P2_CTAS, 256, SMEM_P2_BYTES>>>();

    k_p3<<<NTOK / 4, 256>>>(beta, out);
}